// round 3
// baseline (speedup 1.0000x reference)
#include <cuda_runtime.h>
#include <math.h>
#include <stdint.h>

#define N_NODESK 20000
#define N_HEDGEK 512
#define N_INCK   81920
#define CCH      64
#define BBATCH   8

// ------------------------- device scratch (no allocs allowed) ----------------
__device__ int   g_is64;
__device__ int   g_nodes32[N_INCK];
__device__ int   g_edges32[N_INCK];
__device__ int   g_csr[N_INCK];      // incidence id per CSR slot
__device__ int   g_csre[N_INCK];     // edge id per CSR slot
__device__ int   g_ncnt[N_NODESK];
__device__ int   g_noff[N_NODESK + 1];
__device__ int   g_ncur[N_NODESK];
__device__ int   g_ecnt[N_HEDGEK];
__device__ int   g_eoff[N_HEDGEK + 1];
__device__ float g_agg [N_HEDGEK * BBATCH * CCH];   // [u][b][c]
__device__ float g_q   [BBATCH * N_HEDGEK * CCH];   // [b][u][c]
__device__ float g_kmat[BBATCH * N_HEDGEK * CCH];
__device__ float g_vmat[BBATCH * N_HEDGEK * CCH];
__device__ float g_ax  [N_NODESK * BBATCH];         // attL . x[b][n]
__device__ float g_ae  [N_HEDGEK * BBATCH];         // attR . edge_result[u][b]
__device__ float g_alpha[N_INCK * BBATCH];          // normalized attention
__device__ float g_out1[N_HEDGEK * BBATCH * CCH];   // [u][b][c]

// ------------------------- dtype detection -----------------------------------
// Reference declares int64, but JAX default (x64 disabled) emits int32.
// Real node ids are < 20000; two packed random int32 ids read as int64 are
// ~always >= 2^32. Check the first 16 entries of the node row.
__global__ void detect_kernel(const void* __restrict__ hei) {
    const long long* h64 = (const long long*)hei;
    int ok = 1;
    for (int i = 0; i < 16; i++) {
        long long v = h64[i];
        if (v < 0 || v >= N_NODESK) { ok = 0; break; }
    }
    g_is64 = ok;
}

// ------------------------- CSR construction ---------------------------------
__global__ void zero_kernel() {
    int i = blockIdx.x * blockDim.x + threadIdx.x;
    if (i < N_NODESK) g_ncnt[i] = 0;
    if (i < N_HEDGEK) g_ecnt[i] = 0;
}

__global__ void prep_kernel(const void* __restrict__ hei) {
    int i = blockIdx.x * blockDim.x + threadIdx.x;
    if (i >= N_INCK) return;
    int n, e;
    if (g_is64) {
        const long long* h = (const long long*)hei;
        n = (int)h[i];
        e = (int)h[N_INCK + i];
    } else {
        const int* h = (const int*)hei;
        n = h[i];
        e = h[N_INCK + i];
    }
    // defensive clamp: never allow OOB writes even if detection is wrong
    n = min(max(n, 0), N_NODESK - 1);
    e = min(max(e, 0), N_HEDGEK - 1);
    g_nodes32[i] = n;
    g_edges32[i] = e;
    atomicAdd(&g_ncnt[n], 1);
    atomicAdd(&g_ecnt[e], 1);
}

// single-block exclusive scan (warp-scan based). mode 0: nodes, mode 1: edges
__global__ void scan_kernel(int mode) {
    const int* cnt = mode ? g_ecnt : g_ncnt;
    int* off = mode ? g_eoff : g_noff;
    int* cur = mode ? (int*)0 : g_ncur;
    int n = mode ? N_HEDGEK : N_NODESK;

    __shared__ int wsum[32];
    __shared__ int runningS;
    int lane = threadIdx.x & 31, warp = threadIdx.x >> 5;
    if (threadIdx.x == 0) runningS = 0;
    __syncthreads();
    int nwarps = blockDim.x >> 5;
    for (int base = 0; base < n; base += blockDim.x) {
        int i = base + threadIdx.x;
        int v = (i < n) ? cnt[i] : 0;
        int s = v;
        #pragma unroll
        for (int d = 1; d < 32; d <<= 1) {
            int t = __shfl_up_sync(0xffffffffu, s, d);
            if (lane >= d) s += t;
        }
        if (lane == 31) wsum[warp] = s;
        __syncthreads();
        if (warp == 0) {
            int ws = (lane < nwarps) ? wsum[lane] : 0;
            #pragma unroll
            for (int d = 1; d < 32; d <<= 1) {
                int t = __shfl_up_sync(0xffffffffu, ws, d);
                if (lane >= d) ws += t;
            }
            wsum[lane] = ws;
        }
        __syncthreads();
        int warpoff = (warp == 0) ? 0 : wsum[warp - 1];
        int excl = runningS + warpoff + s - v;
        if (i < n) {
            off[i] = excl;
            if (cur) cur[i] = excl;
        }
        __syncthreads();
        if (threadIdx.x == blockDim.x - 1) runningS += wsum[nwarps - 1];
        __syncthreads();
    }
    if (threadIdx.x == 0) off[n] = runningS;
}

__global__ void fill_kernel() {
    int i = blockIdx.x * blockDim.x + threadIdx.x;
    if (i >= N_INCK) return;
    int n = g_nodes32[i];
    int slot = atomicAdd(&g_ncur[n], 1);
    g_csr[slot] = i;
    g_csre[slot] = g_edges32[i];
}

// ------------------------- agg: sum of x over each hyperedge -----------------
// edges are sorted -> incidences of edge u are exactly [eoff[u], eoff[u+1])
__global__ __launch_bounds__(512) void agg_kernel(const float* __restrict__ x) {
    __shared__ int nidx[192];
    int u = blockIdx.x;
    int s = g_eoff[u], e = g_eoff[u + 1];
    int b = threadIdx.x >> 6, c = threadIdx.x & 63;
    float acc = 0.f;
    for (int base = s; base < e; base += 192) {
        int cnt = min(192, e - base);
        __syncthreads();
        if (threadIdx.x < cnt) nidx[threadIdx.x] = g_nodes32[base + threadIdx.x];
        __syncthreads();
        for (int t = 0; t < cnt; t++) {
            acc += x[((size_t)b * N_NODESK + nidx[t]) * CCH + c];
        }
    }
    g_agg[u * (BBATCH * CCH) + threadIdx.x] = acc;
}

// ------------------------- a_x[n][b] = attL . x[b][n] ------------------------
__global__ __launch_bounds__(256) void ax_kernel(const float* __restrict__ x,
                                                 const float* __restrict__ att) {
    int n = blockIdx.x;
    int w = threadIdx.x >> 5;  // batch
    int l = threadIdx.x & 31;
    const float* row = x + ((size_t)w * N_NODESK + n) * CCH;
    float p = att[l] * row[l] + att[l + 32] * row[l + 32];
    #pragma unroll
    for (int d = 16; d; d >>= 1) p += __shfl_xor_sync(0xffffffffu, p, d);
    if (l == 0) g_ax[n * BBATCH + w] = p;
}

// ------------------------- q,k,v = agg @ W^T + b -----------------------------
__global__ __launch_bounds__(512) void qkv_kernel(
    const float* __restrict__ Wq, const float* __restrict__ bq,
    const float* __restrict__ Wk, const float* __restrict__ bk,
    const float* __restrict__ Wv, const float* __restrict__ bv) {
    __shared__ float WT[64 * 65];
    __shared__ float aggS[512];
    int u = blockIdx.x;
    aggS[threadIdx.x] = g_agg[u * 512 + threadIdx.x];
    int b = threadIdx.x >> 6, c = threadIdx.x & 63;

    const float* Ws[3] = {Wq, Wk, Wv};
    const float* bs[3] = {bq, bk, bv};
    float* outs[3] = {g_q, g_kmat, g_vmat};
    for (int m = 0; m < 3; m++) {
        __syncthreads();
        for (int idx = threadIdx.x; idx < 4096; idx += 512) {
            // WT[d][c] = W[c][d], padded rows (65) -> conflict-free r/w
            WT[(idx & 63) * 65 + (idx >> 6)] = Ws[m][idx];
        }
        __syncthreads();
        float acc = bs[m][c];
        #pragma unroll
        for (int d = 0; d < 64; d++) acc += aggS[b * 64 + d] * WT[d * 65 + c];
        outs[m][((size_t)b * N_HEDGEK + u) * CCH + c] = acc;
    }
}

// ------------------------- masked edge-edge attention ------------------------
// computes softmax(q k^T/8 - (1-adj)*500) @ v per batch, but only emits
// a_e[u][b] = attR . edge_result[u][b]  (edge_result itself is never needed)
__global__ __launch_bounds__(256) void attn_kernel(const float* __restrict__ adj,
                                                   const float* __restrict__ att) {
    __shared__ float qS[16 * 64];
    __shared__ float kv[32 * 65];
    __shared__ float sc[16 * 512];
    __shared__ float red[16][2];
    int b = blockIdx.y;
    int u0 = blockIdx.x * 16;
    int tid = threadIdx.x;
    const float* qb = g_q    + (size_t)b * N_HEDGEK * CCH;
    const float* kb = g_kmat + (size_t)b * N_HEDGEK * CCH;
    const float* vb = g_vmat + (size_t)b * N_HEDGEK * CCH;

    for (int idx = tid; idx < 16 * 64; idx += 256) qS[idx] = qb[u0 * 64 + idx];

    int j = tid & 31, g = tid >> 5;           // QK mapping: col j, rows g, g+8
    int r0 = g, r1 = g + 8;
    for (int vt = 0; vt < 16; vt++) {
        __syncthreads();
        for (int idx = tid; idx < 32 * 64; idx += 256) {
            int row = idx >> 6, col = idx & 63;
            kv[row * 65 + col] = kb[(vt * 32 + row) * 64 + col];
        }
        __syncthreads();
        float a0 = 0.f, a1 = 0.f;
        #pragma unroll
        for (int c = 0; c < 64; c++) {
            float kvv = kv[j * 65 + c];
            a0 += qS[r0 * 64 + c] * kvv;
            a1 += qS[r1 * 64 + c] * kvv;
        }
        int v = vt * 32 + j;
        sc[r0 * 512 + v] = a0 * 0.125f - (1.f - adj[(u0 + r0) * 512 + v]) * 500.f;
        sc[r1 * 512 + v] = a1 * 0.125f - (1.f - adj[(u0 + r1) * 512 + v]) * 500.f;
    }
    __syncthreads();

    // softmax: warp w handles rows w and w+8
    int lane = tid & 31, w = tid >> 5;
    for (int rr = 0; rr < 2; rr++) {
        int r = w + rr * 8;
        float m = -1e30f;
        for (int vv = lane; vv < 512; vv += 32) m = fmaxf(m, sc[r * 512 + vv]);
        #pragma unroll
        for (int d = 16; d; d >>= 1) m = fmaxf(m, __shfl_xor_sync(0xffffffffu, m, d));
        float den = 0.f;
        for (int vv = lane; vv < 512; vv += 32) den += __expf(sc[r * 512 + vv] - m);
        #pragma unroll
        for (int d = 16; d; d >>= 1) den += __shfl_xor_sync(0xffffffffu, den, d);
        float inv = 1.f / den;
        for (int vv = lane; vv < 512; vv += 32)
            sc[r * 512 + vv] = __expf(sc[r * 512 + vv] - m) * inv;
    }

    // PV: thread owns col c, rows {g2, g2+4, g2+8, g2+12}
    int c = tid & 63, g2 = tid >> 6;
    float acc[4] = {0.f, 0.f, 0.f, 0.f};
    for (int vt = 0; vt < 16; vt++) {
        __syncthreads();
        for (int idx = tid; idx < 32 * 64; idx += 256) {
            int row = idx >> 6, col = idx & 63;
            kv[row * 65 + col] = vb[(vt * 32 + row) * 64 + col];
        }
        __syncthreads();
        for (int vv = 0; vv < 32; vv++) {
            float vval = kv[vv * 65 + c];
            #pragma unroll
            for (int ri = 0; ri < 4; ri++)
                acc[ri] += sc[(g2 + ri * 4) * 512 + vt * 32 + vv] * vval;
        }
    }

    // epilogue: a_e[u][b] = sum_c attR[c] * edge_result_row[c]
    float attR = att[64 + c];
    #pragma unroll
    for (int ri = 0; ri < 4; ri++) {
        float p = attR * acc[ri];
        #pragma unroll
        for (int d = 16; d; d >>= 1) p += __shfl_xor_sync(0xffffffffu, p, d);
        if (lane == 0) red[g2 + ri * 4][w & 1] = p;
    }
    __syncthreads();
    if (tid < 16) g_ae[(u0 + tid) * BBATCH + b] = red[tid][0] + red[tid][1];
}

// ------------------------- per-node segment softmax --------------------------
// one warp per node; lane -> (b = lane&7, stride-4 over the node's incidences)
__global__ __launch_bounds__(256) void node_softmax_kernel() {
    int node = blockIdx.x * (blockDim.x >> 5) + (threadIdx.x >> 5);
    if (node >= N_NODESK) return;
    int lane = threadIdx.x & 31;
    int b = lane & 7, sub = lane >> 3;
    int s = g_noff[node], e = g_noff[node + 1];
    if (s == e) return;
    float axv = g_ax[node * BBATCH + b];

    float m = -1e30f;
    for (int p = s + sub; p < e; p += 4) {
        float v = axv + g_ae[g_csre[p] * BBATCH + b];
        v = v >= 0.f ? v : 0.2f * v;
        m = fmaxf(m, v);
    }
    m = fmaxf(m, __shfl_xor_sync(0xffffffffu, m, 8));
    m = fmaxf(m, __shfl_xor_sync(0xffffffffu, m, 16));
    float den = 0.f;
    for (int p = s + sub; p < e; p += 4) {
        float v = axv + g_ae[g_csre[p] * BBATCH + b];
        v = v >= 0.f ? v : 0.2f * v;
        den += __expf(v - m);
    }
    den += __shfl_xor_sync(0xffffffffu, den, 8);
    den += __shfl_xor_sync(0xffffffffu, den, 16);
    float inv = 1.f / (den + 1e-16f);
    for (int p = s + sub; p < e; p += 4) {
        int i = g_csr[p];
        float v = axv + g_ae[g_csre[p] * BBATCH + b];
        v = v >= 0.f ? v : 0.2f * v;
        g_alpha[i * BBATCH + b] = __expf(v - m) * inv;
    }
}

// ------------------------- stage 1: nodes -> hyperedges ----------------------
__global__ __launch_bounds__(512) void out1_kernel(const float* __restrict__ x) {
    __shared__ int nidx[192];
    int u = blockIdx.x;
    int s = g_eoff[u], e = g_eoff[u + 1];
    int b = threadIdx.x >> 6, c = threadIdx.x & 63;
    float acc = 0.f;
    for (int base = s; base < e; base += 192) {
        int cnt = min(192, e - base);
        __syncthreads();
        if (threadIdx.x < cnt) nidx[threadIdx.x] = g_nodes32[base + threadIdx.x];
        __syncthreads();
        for (int t = 0; t < cnt; t++) {
            float wgt = g_alpha[(base + t) * BBATCH + b];
            acc += wgt * x[((size_t)b * N_NODESK + nidx[t]) * CCH + c];
        }
    }
    float inv = (e > s) ? (1.f / (float)(e - s)) : 0.f;  // Bn = 1/deg_e
    g_out1[u * (BBATCH * CCH) + threadIdx.x] = acc * inv;
}

// ------------------------- stage 2: hyperedges -> nodes ----------------------
__global__ __launch_bounds__(512) void out2_kernel(float* __restrict__ out) {
    int n = blockIdx.x;
    int b = threadIdx.x >> 6, c = threadIdx.x & 63;
    int s = g_noff[n], e = g_noff[n + 1];
    float acc = 0.f;
    for (int p = s; p < e; p++) {
        int i = g_csr[p];
        float wgt = g_alpha[i * BBATCH + b];
        acc += wgt * g_out1[g_csre[p] * (BBATCH * CCH) + threadIdx.x];
    }
    out[((size_t)b * N_NODESK + n) * CCH + c] = (float)(e - s) * acc;
}

// ------------------------- launch ---------------------------------------------
extern "C" void kernel_launch(void* const* d_in, const int* in_sizes, int n_in,
                              void* d_out, int out_size) {
    const float* x   = (const float*)d_in[0];
    const float* Wq  = (const float*)d_in[1];
    const float* bq  = (const float*)d_in[2];
    const float* Wk  = (const float*)d_in[3];
    const float* bk  = (const float*)d_in[4];
    const float* Wv  = (const float*)d_in[5];
    const float* bv  = (const float*)d_in[6];
    const float* att = (const float*)d_in[7];
    const float* adj = (const float*)d_in[8];
    const void*  hei = (const void*)d_in[9];
    float* out = (float*)d_out;

    detect_kernel<<<1, 1>>>(hei);
    zero_kernel<<<(N_NODESK + 255) / 256, 256>>>();
    prep_kernel<<<(N_INCK + 255) / 256, 256>>>(hei);
    scan_kernel<<<1, 1024>>>(0);   // node offsets + cursor
    scan_kernel<<<1, 1024>>>(1);   // edge offsets
    fill_kernel<<<(N_INCK + 255) / 256, 256>>>();

    agg_kernel<<<N_HEDGEK, 512>>>(x);
    ax_kernel<<<N_NODESK, 256>>>(x, att);
    qkv_kernel<<<N_HEDGEK, 512>>>(Wq, bq, Wk, bk, Wv, bv);
    attn_kernel<<<dim3(N_HEDGEK / 16, BBATCH), 256>>>(adj, att);
    node_softmax_kernel<<<(N_NODESK + 7) / 8, 256>>>();
    out1_kernel<<<N_HEDGEK, 512>>>(x);
    out2_kernel<<<N_NODESK, 512>>>(out);
}

// round 4
// speedup vs baseline: 1.2107x; 1.2107x over previous
#include <cuda_runtime.h>
#include <math.h>
#include <stdint.h>

#define N_NODESK 20000
#define N_HEDGEK 512
#define N_INCK   81920
#define CCH      64
#define BBATCH   8
#define NBLK     79        // ceil(20000/256)

// ------------------------- device scratch (no allocs allowed) ----------------
__device__ int   g_is64;
__device__ int   g_nodes32[N_INCK];
__device__ int   g_edges32[N_INCK];
__device__ int   g_csr[N_INCK];      // incidence id per CSR slot
__device__ int   g_csre[N_INCK];     // edge id per CSR slot
__device__ int   g_ncnt[N_NODESK];
__device__ int   g_noff[N_NODESK + 1];
__device__ int   g_ncur[N_NODESK];   // doubles as local-scan temp
__device__ int   g_ecnt[N_HEDGEK];
__device__ int   g_eoff[N_HEDGEK + 1];
__device__ int   g_bsum[128];
__device__ int   g_boff[128];
__device__ float g_aggp[2 * N_HEDGEK * BBATCH * CCH]; // 2 halves of [u][b][c]
__device__ float g_q   [BBATCH * N_HEDGEK * CCH];     // [b][u][c]
__device__ float g_kmat[BBATCH * N_HEDGEK * CCH];
__device__ float g_w   [BBATCH * N_HEDGEK];           // attR.(v_row) per [b][u]
__device__ float g_ae  [N_HEDGEK * BBATCH];           // attR.edge_result[u][b]
__device__ float g_alpha[N_INCK * BBATCH];            // normalized attention
__device__ float g_out1[N_HEDGEK * BBATCH * CCH];     // [u][b][c] (atomic acc)

__device__ __forceinline__ int warp_iscan(int v, int lane) {
    #pragma unroll
    for (int d = 1; d < 32; d <<= 1) {
        int t = __shfl_up_sync(0xffffffffu, v, d);
        if (lane >= d) v += t;
    }
    return v;
}

// ------------------------- zero + dtype detect -------------------------------
__global__ void zero_detect_kernel(const void* __restrict__ hei) {
    int i = blockIdx.x * blockDim.x + threadIdx.x;
    if (i < N_NODESK) g_ncnt[i] = 0;
    if (i < N_HEDGEK) g_ecnt[i] = 0;
    for (int j = i; j < N_HEDGEK * BBATCH * CCH; j += NBLK * 256) g_out1[j] = 0.f;
    if (i == 0) {
        // int64-declared index may materialize as int32 (JAX x64 off).
        const long long* h64 = (const long long*)hei;
        int ok = 1;
        for (int k = 0; k < 16; k++) {
            long long v = h64[k];
            if (v < 0 || v >= N_NODESK) { ok = 0; break; }
        }
        g_is64 = ok;
    }
}

__global__ void prep_kernel(const void* __restrict__ hei) {
    int i = blockIdx.x * blockDim.x + threadIdx.x;
    if (i >= N_INCK) return;
    int n, e;
    if (g_is64) {
        const long long* h = (const long long*)hei;
        n = (int)h[i];
        e = (int)h[N_INCK + i];
    } else {
        const int* h = (const int*)hei;
        n = h[i];
        e = h[N_INCK + i];
    }
    n = min(max(n, 0), N_NODESK - 1);
    e = min(max(e, 0), N_HEDGEK - 1);
    g_nodes32[i] = n;
    g_edges32[i] = e;
    atomicAdd(&g_ncnt[n], 1);
    atomicAdd(&g_ecnt[e], 1);
}

// ------------------------- 3-phase node scan (parallel) ----------------------
__global__ void scan_local_kernel() {   // NBLK blocks x 256
    __shared__ int wsum[8];
    int t = threadIdx.x, lane = t & 31, warp = t >> 5;
    int i = blockIdx.x * 256 + t;
    int v = (i < N_NODESK) ? g_ncnt[i] : 0;
    int s = warp_iscan(v, lane);
    if (lane == 31) wsum[warp] = s;
    __syncthreads();
    if (warp == 0) {
        int ws = (lane < 8) ? wsum[lane] : 0;
        ws = warp_iscan(ws, lane);
        if (lane < 8) wsum[lane] = ws;
    }
    __syncthreads();
    int excl = (warp ? wsum[warp - 1] : 0) + s - v;
    if (i < N_NODESK) g_ncur[i] = excl;        // block-local exclusive
    if (t == 255) g_bsum[blockIdx.x] = wsum[7];
}

__global__ void scan_mid_kernel() {     // 1 block x 512: edges + block sums
    __shared__ int wsum[16];
    int t = threadIdx.x, lane = t & 31, warp = t >> 5;
    int v = g_ecnt[t];
    int s = warp_iscan(v, lane);
    if (lane == 31) wsum[warp] = s;
    __syncthreads();
    if (warp == 0) {
        int ws = (lane < 16) ? wsum[lane] : 0;
        ws = warp_iscan(ws, lane);
        if (lane < 16) wsum[lane] = ws;
    }
    __syncthreads();
    int excl = (warp ? wsum[warp - 1] : 0) + s - v;
    g_eoff[t] = excl;
    if (t == 511) g_eoff[512] = excl + v;

    if (warp == 0) {                    // scan 79 block sums
        int running = 0;
        #pragma unroll
        for (int k = 0; k < 3; k++) {
            int idx = k * 32 + lane;
            int val = (idx < NBLK) ? g_bsum[idx] : 0;
            int sc2 = warp_iscan(val, lane);
            if (idx < NBLK) g_boff[idx] = running + sc2 - val;
            running += __shfl_sync(0xffffffffu, sc2, 31);
        }
    }
}

__global__ void scan_add_kernel() {     // NBLK blocks x 256
    int i = blockIdx.x * 256 + threadIdx.x;
    if (i < N_NODESK) {
        int val = g_ncur[i] + g_boff[blockIdx.x];
        g_noff[i] = val;
        g_ncur[i] = val;
    }
    if (blockIdx.x == 0 && threadIdx.x == 0) g_noff[N_NODESK] = N_INCK;
}

__global__ void fill_kernel() {
    int i = blockIdx.x * blockDim.x + threadIdx.x;
    if (i >= N_INCK) return;
    int n = g_nodes32[i];
    int slot = atomicAdd(&g_ncur[n], 1);
    g_csr[slot] = i;
    g_csre[slot] = g_edges32[i];
}

// ------------------------- agg: sum of x over each hyperedge (split 2) -------
__global__ __launch_bounds__(512) void agg_kernel(const float* __restrict__ x) {
    __shared__ int nidx[96];
    int u = blockIdx.x >> 1, half = blockIdx.x & 1;
    int s = g_eoff[u], e = g_eoff[u + 1], len = e - s;
    int h0 = s + (half ? len / 2 : 0);
    int h1 = half ? e : s + len / 2;
    int b = threadIdx.x >> 6, c = threadIdx.x & 63;
    float acc = 0.f;
    for (int base = h0; base < h1; base += 96) {
        int cnt = min(96, h1 - base);
        __syncthreads();
        if (threadIdx.x < cnt) nidx[threadIdx.x] = g_nodes32[base + threadIdx.x];
        __syncthreads();
        for (int t = 0; t < cnt; t++) {
            acc += x[((size_t)b * N_NODESK + nidx[t]) * CCH + c];
        }
    }
    g_aggp[((size_t)half * N_HEDGEK + u) * 512 + threadIdx.x] = acc;
}

// ------------------------- q,k = agg @ W^T + b ;  w = agg . wv + cb ----------
__global__ __launch_bounds__(512) void qkv_kernel(
    const float* __restrict__ Wq, const float* __restrict__ bq,
    const float* __restrict__ Wk, const float* __restrict__ bk,
    const float* __restrict__ Wv, const float* __restrict__ bv,
    const float* __restrict__ att) {
    __shared__ float WT[64 * 65];
    __shared__ float aggS[512];
    __shared__ float wvS[64];
    __shared__ float wred[16];
    __shared__ float cbS;
    int u = blockIdx.x;
    aggS[threadIdx.x] = g_aggp[u * 512 + threadIdx.x]
                      + g_aggp[(size_t)N_HEDGEK * 512 + u * 512 + threadIdx.x];
    int b = threadIdx.x >> 6, c = threadIdx.x & 63;

    const float* Ws[2] = {Wq, Wk};
    const float* bs[2] = {bq, bk};
    float* outs[2] = {g_q, g_kmat};
    for (int m = 0; m < 2; m++) {
        __syncthreads();
        for (int idx = threadIdx.x; idx < 4096; idx += 512)
            WT[(idx & 63) * 65 + (idx >> 6)] = Ws[m][idx];
        __syncthreads();
        float acc = bs[m][c];
        #pragma unroll
        for (int d = 0; d < 64; d++) acc += aggS[b * 64 + d] * WT[d * 65 + c];
        outs[m][((size_t)b * N_HEDGEK + u) * CCH + c] = acc;
    }

    // wv[c] = sum_d attR[d]*Wv[d][c];  cb = attR.bv
    __syncthreads();
    if (threadIdx.x < 64) {
        float s = 0.f;
        for (int d = 0; d < 64; d++) s += att[64 + d] * Wv[d * 64 + threadIdx.x];
        wvS[threadIdx.x] = s;
    }
    if (threadIdx.x == 0) {
        float s = 0.f;
        for (int d = 0; d < 64; d++) s += att[64 + d] * bv[d];
        cbS = s;
    }
    __syncthreads();
    float part = aggS[threadIdx.x] * wvS[c];
    #pragma unroll
    for (int d = 16; d; d >>= 1) part += __shfl_xor_sync(0xffffffffu, part, d);
    if ((threadIdx.x & 31) == 0) wred[threadIdx.x >> 5] = part;
    __syncthreads();
    if (c == 0) g_w[(size_t)b * N_HEDGEK + u] = wred[b * 2] + wred[b * 2 + 1] + cbS;
}

// ------------------------- masked edge-edge attention ------------------------
// a_e[u][b] = sum_v softmax(qk/8 - (1-adj)*500)[u,v] * w[v][b]
__global__ __launch_bounds__(256) void attn_kernel(const float* __restrict__ adj) {
    __shared__ float qS[16 * 64];
    __shared__ float kv[32 * 65];
    __shared__ float sc[16 * 512];
    __shared__ float wS[512];
    int b = blockIdx.y;
    int u0 = blockIdx.x * 16;
    int tid = threadIdx.x;
    const float* qb = g_q    + (size_t)b * N_HEDGEK * CCH;
    const float* kb = g_kmat + (size_t)b * N_HEDGEK * CCH;

    for (int idx = tid; idx < 16 * 64; idx += 256) qS[idx] = qb[u0 * 64 + idx];
    for (int idx = tid; idx < 512; idx += 256) wS[idx] = g_w[(size_t)b * N_HEDGEK + idx];

    int j = tid & 31, g = tid >> 5;
    int r0 = g, r1 = g + 8;
    for (int vt = 0; vt < 16; vt++) {
        __syncthreads();
        for (int idx = tid; idx < 32 * 64; idx += 256) {
            int row = idx >> 6, col = idx & 63;
            kv[row * 65 + col] = kb[(vt * 32 + row) * 64 + col];
        }
        __syncthreads();
        float a0 = 0.f, a1 = 0.f;
        #pragma unroll
        for (int c = 0; c < 64; c++) {
            float kvv = kv[j * 65 + c];
            a0 += qS[r0 * 64 + c] * kvv;
            a1 += qS[r1 * 64 + c] * kvv;
        }
        int v = vt * 32 + j;
        sc[r0 * 512 + v] = a0 * 0.125f - (1.f - adj[(u0 + r0) * 512 + v]) * 500.f;
        sc[r1 * 512 + v] = a1 * 0.125f - (1.f - adj[(u0 + r1) * 512 + v]) * 500.f;
    }
    __syncthreads();

    // fused softmax + weighted sum (warp w handles rows w and w+8)
    int lane = tid & 31, w = tid >> 5;
    #pragma unroll
    for (int rr = 0; rr < 2; rr++) {
        int r = w + rr * 8;
        float m = -1e30f;
        for (int vv = lane; vv < 512; vv += 32) m = fmaxf(m, sc[r * 512 + vv]);
        #pragma unroll
        for (int d = 16; d; d >>= 1) m = fmaxf(m, __shfl_xor_sync(0xffffffffu, m, d));
        float den = 0.f, num = 0.f;
        for (int vv = lane; vv < 512; vv += 32) {
            float e = __expf(sc[r * 512 + vv] - m);
            den += e;
            num += e * wS[vv];
        }
        #pragma unroll
        for (int d = 16; d; d >>= 1) {
            den += __shfl_xor_sync(0xffffffffu, den, d);
            num += __shfl_xor_sync(0xffffffffu, num, d);
        }
        if (lane == 0) g_ae[(u0 + r) * BBATCH + b] = num / den;
    }
}

// ------------------------- per-node segment softmax (ax fused) ---------------
__global__ __launch_bounds__(256) void node_softmax_kernel(
    const float* __restrict__ x, const float* __restrict__ att) {
    __shared__ float attS[64];
    if (threadIdx.x < 64) attS[threadIdx.x] = att[threadIdx.x];
    __syncthreads();
    int node = blockIdx.x * 8 + (threadIdx.x >> 5);
    if (node >= N_NODESK) return;
    int lane = threadIdx.x & 31;
    int b = lane & 7, sub = lane >> 3;
    int s = g_noff[node], e = g_noff[node + 1];
    if (s == e) return;

    // axv = attL . x[b][node], split over 4 sub-lanes then reduced
    const float4* row = (const float4*)(x + ((size_t)b * N_NODESK + node) * CCH + sub * 16);
    float p = 0.f;
    #pragma unroll
    for (int k = 0; k < 4; k++) {
        float4 v4 = row[k];
        const float* a = attS + sub * 16 + k * 4;
        p += v4.x * a[0] + v4.y * a[1] + v4.z * a[2] + v4.w * a[3];
    }
    p += __shfl_xor_sync(0xffffffffu, p, 8);
    p += __shfl_xor_sync(0xffffffffu, p, 16);
    float axv = p;

    float m = -1e30f;
    for (int q = s + sub; q < e; q += 4) {
        float v = axv + g_ae[g_csre[q] * BBATCH + b];
        v = v >= 0.f ? v : 0.2f * v;
        m = fmaxf(m, v);
    }
    m = fmaxf(m, __shfl_xor_sync(0xffffffffu, m, 8));
    m = fmaxf(m, __shfl_xor_sync(0xffffffffu, m, 16));
    float den = 0.f;
    for (int q = s + sub; q < e; q += 4) {
        float v = axv + g_ae[g_csre[q] * BBATCH + b];
        v = v >= 0.f ? v : 0.2f * v;
        den += __expf(v - m);
    }
    den += __shfl_xor_sync(0xffffffffu, den, 8);
    den += __shfl_xor_sync(0xffffffffu, den, 16);
    float inv = 1.f / (den + 1e-16f);
    for (int q = s + sub; q < e; q += 4) {
        int i = g_csr[q];
        float v = axv + g_ae[g_csre[q] * BBATCH + b];
        v = v >= 0.f ? v : 0.2f * v;
        g_alpha[i * BBATCH + b] = __expf(v - m) * inv;
    }
}

// ------------------------- stage 1: nodes -> hyperedges (split 2, atomic) ----
__global__ __launch_bounds__(512) void out1_kernel(const float* __restrict__ x) {
    __shared__ int nidx[96];
    int u = blockIdx.x >> 1, half = blockIdx.x & 1;
    int s = g_eoff[u], e = g_eoff[u + 1], len = e - s;
    int h0 = s + (half ? len / 2 : 0);
    int h1 = half ? e : s + len / 2;
    int b = threadIdx.x >> 6, c = threadIdx.x & 63;
    float acc = 0.f;
    for (int base = h0; base < h1; base += 96) {
        int cnt = min(96, h1 - base);
        __syncthreads();
        if (threadIdx.x < cnt) nidx[threadIdx.x] = g_nodes32[base + threadIdx.x];
        __syncthreads();
        for (int t = 0; t < cnt; t++) {
            float wgt = g_alpha[(base + t) * BBATCH + b];
            acc += wgt * x[((size_t)b * N_NODESK + nidx[t]) * CCH + c];
        }
    }
    float inv = (len > 0) ? (1.f / (float)len) : 0.f;   // Bn = 1/deg_e
    atomicAdd(&g_out1[u * (BBATCH * CCH) + threadIdx.x], acc * inv);
}

// ------------------------- stage 2: hyperedges -> nodes ----------------------
__global__ __launch_bounds__(512) void out2_kernel(float* __restrict__ out) {
    int n = blockIdx.x;
    int b = threadIdx.x >> 6, c = threadIdx.x & 63;
    int s = g_noff[n], e = g_noff[n + 1];
    float acc = 0.f;
    for (int p = s; p < e; p++) {
        int i = g_csr[p];
        float wgt = g_alpha[i * BBATCH + b];
        acc += wgt * g_out1[g_csre[p] * (BBATCH * CCH) + threadIdx.x];
    }
    out[((size_t)b * N_NODESK + n) * CCH + c] = (float)(e - s) * acc;
}

// ------------------------- launch --------------------------------------------
extern "C" void kernel_launch(void* const* d_in, const int* in_sizes, int n_in,
                              void* d_out, int out_size) {
    const float* x   = (const float*)d_in[0];
    const float* Wq  = (const float*)d_in[1];
    const float* bq  = (const float*)d_in[2];
    const float* Wk  = (const float*)d_in[3];
    const float* bk  = (const float*)d_in[4];
    const float* Wv  = (const float*)d_in[5];
    const float* bv  = (const float*)d_in[6];
    const float* att = (const float*)d_in[7];
    const float* adj = (const float*)d_in[8];
    const void*  hei = (const void*)d_in[9];
    float* out = (float*)d_out;

    zero_detect_kernel<<<NBLK, 256>>>(hei);
    prep_kernel<<<(N_INCK + 255) / 256, 256>>>(hei);
    scan_local_kernel<<<NBLK, 256>>>();
    scan_mid_kernel<<<1, 512>>>();
    scan_add_kernel<<<NBLK, 256>>>();
    fill_kernel<<<(N_INCK + 255) / 256, 256>>>();

    agg_kernel<<<N_HEDGEK * 2, 512>>>(x);
    qkv_kernel<<<N_HEDGEK, 512>>>(Wq, bq, Wk, bk, Wv, bv, att);
    attn_kernel<<<dim3(N_HEDGEK / 16, BBATCH), 256>>>(adj);
    node_softmax_kernel<<<(N_NODESK + 7) / 8, 256>>>(x, att);
    out1_kernel<<<N_HEDGEK * 2, 512>>>(x);
    out2_kernel<<<N_NODESK, 512>>>(out);
}

// round 5
// speedup vs baseline: 1.2993x; 1.0731x over previous
#include <cuda_runtime.h>
#include <math.h>
#include <stdint.h>

#define N_NODESK 20000
#define N_HEDGEK 512
#define N_INCK   81920
#define CCH      64
#define BBATCH   8
#define NBLK     79        // ceil(20000/256)

// ------------------------- device scratch (no allocs allowed) ----------------
__device__ int   g_nodes32[N_INCK];
__device__ int   g_edges32[N_INCK];
__device__ int   g_csr[N_INCK];      // incidence id per CSR slot
__device__ int   g_csre[N_INCK];     // edge id per CSR slot
__device__ int   g_ncnt[N_NODESK];
__device__ int   g_noff[N_NODESK + 1];
__device__ int   g_ncur[N_NODESK];   // doubles as local-scan temp
__device__ int   g_bsum[128];
__device__ float g_q   [BBATCH * N_HEDGEK * CCH];     // [b][u][c]
__device__ float g_kmat[BBATCH * N_HEDGEK * CCH];
__device__ float g_w   [BBATCH * N_HEDGEK];           // attR.(v row) per [b][u]
__device__ float g_ae  [N_HEDGEK * BBATCH];           // attR.edge_result[u][b]
__device__ float g_alpha[N_INCK * BBATCH];            // normalized attention
__device__ float g_out1[N_HEDGEK * BBATCH * CCH];     // [u][b][c]

__device__ __forceinline__ int warp_iscan(int v, int lane) {
    #pragma unroll
    for (int d = 1; d < 32; d <<= 1) {
        int t = __shfl_up_sync(0xffffffffu, v, d);
        if (lane >= d) v += t;
    }
    return v;
}

// first CSR slot whose edge id >= val (edges32 is sorted by construction)
__device__ __forceinline__ int edge_lower_bound(int val) {
    int lo = 0, hi = N_INCK;
    while (lo < hi) {
        int mid = (lo + hi) >> 1;
        if (g_edges32[mid] < val) lo = mid + 1; else hi = mid;
    }
    return lo;
}

// ------------------------- zero node counters --------------------------------
__global__ void zero_kernel() {
    int i = blockIdx.x * blockDim.x + threadIdx.x;
    if (i < N_NODESK) g_ncnt[i] = 0;
}

// ------------------------- decode indices (+ per-block dtype detect) ---------
// Reference declares int64, but JAX default (x64 off) materializes int32.
__global__ void prep_kernel(const void* __restrict__ hei) {
    __shared__ int is64S;
    if (threadIdx.x == 0) {
        const long long* h64 = (const long long*)hei;
        int ok = 1;
        for (int k = 0; k < 16; k++) {
            long long v = h64[k];
            if (v < 0 || v >= N_NODESK) { ok = 0; break; }
        }
        is64S = ok;
    }
    __syncthreads();
    int i = blockIdx.x * blockDim.x + threadIdx.x;
    if (i >= N_INCK) return;
    int n, e;
    if (is64S) {
        const long long* h = (const long long*)hei;
        n = (int)h[i];
        e = (int)h[N_INCK + i];
    } else {
        const int* h = (const int*)hei;
        n = h[i];
        e = h[N_INCK + i];
    }
    n = min(max(n, 0), N_NODESK - 1);
    e = min(max(e, 0), N_HEDGEK - 1);
    g_nodes32[i] = n;
    g_edges32[i] = e;
    atomicAdd(&g_ncnt[n], 1);
}

// ------------------------- node-offset scan (2 kernels) ----------------------
__global__ void scan_local_kernel() {   // NBLK x 256: block-local exclusive
    __shared__ int wsum[8];
    int t = threadIdx.x, lane = t & 31, warp = t >> 5;
    int i = blockIdx.x * 256 + t;
    int v = (i < N_NODESK) ? g_ncnt[i] : 0;
    int s = warp_iscan(v, lane);
    if (lane == 31) wsum[warp] = s;
    __syncthreads();
    if (warp == 0) {
        int ws = (lane < 8) ? wsum[lane] : 0;
        ws = warp_iscan(ws, lane);
        if (lane < 8) wsum[lane] = ws;
    }
    __syncthreads();
    int excl = (warp ? wsum[warp - 1] : 0) + s - v;
    if (i < N_NODESK) g_ncur[i] = excl;
    if (t == 255) g_bsum[blockIdx.x] = wsum[7];
}

__global__ void scan_add_kernel() {     // NBLK x 256: add block offset
    __shared__ int boffS;
    if (threadIdx.x < 32) {
        int lane = threadIdx.x;
        int sum = 0;
        for (int base = 0; base < blockIdx.x; base += 32) {
            int idx = base + lane;
            sum += (idx < blockIdx.x) ? g_bsum[idx] : 0;
        }
        #pragma unroll
        for (int d = 16; d; d >>= 1) sum += __shfl_xor_sync(0xffffffffu, sum, d);
        if (lane == 0) boffS = sum;
    }
    __syncthreads();
    int i = blockIdx.x * 256 + threadIdx.x;
    if (i < N_NODESK) {
        int val = g_ncur[i] + boffS;
        g_noff[i] = val;
        g_ncur[i] = val;
    }
    if (blockIdx.x == 0 && threadIdx.x == 0) g_noff[N_NODESK] = N_INCK;
}

__global__ void fill_kernel() {
    int i = blockIdx.x * blockDim.x + threadIdx.x;
    if (i >= N_INCK) return;
    int n = g_nodes32[i];
    int slot = atomicAdd(&g_ncur[n], 1);
    g_csr[slot] = i;
    g_csre[slot] = g_edges32[i];
}

// ------------------------- fused agg + q,k,w ---------------------------------
// one block per hyperedge u; segment bounds via binary search (no scan dep)
__global__ __launch_bounds__(512) void aggqkv_kernel(
    const float* __restrict__ x,
    const float* __restrict__ Wq, const float* __restrict__ bq,
    const float* __restrict__ Wk, const float* __restrict__ bk,
    const float* __restrict__ Wv, const float* __restrict__ bv,
    const float* __restrict__ att) {
    __shared__ float WT[64 * 65];
    __shared__ float aggS[512];
    __shared__ float wvS[64];
    __shared__ float wred[16];
    __shared__ float cbS;
    __shared__ int nidx[96];
    __shared__ int seS[2];
    int u = blockIdx.x;
    if (threadIdx.x == 0) seS[0] = edge_lower_bound(u);
    if (threadIdx.x == 32) seS[1] = edge_lower_bound(u + 1);
    __syncthreads();
    int s = seS[0], e = seS[1];
    int b = threadIdx.x >> 6, c = threadIdx.x & 63;

    float acc = 0.f;
    for (int base = s; base < e; base += 96) {
        int cnt = min(96, e - base);
        __syncthreads();
        if (threadIdx.x < cnt) nidx[threadIdx.x] = g_nodes32[base + threadIdx.x];
        __syncthreads();
        for (int t = 0; t < cnt; t++)
            acc += x[((size_t)b * N_NODESK + nidx[t]) * CCH + c];
    }
    __syncthreads();
    aggS[threadIdx.x] = acc;

    const float* Ws[2] = {Wq, Wk};
    const float* bs[2] = {bq, bk};
    float* outs[2] = {g_q, g_kmat};
    for (int m = 0; m < 2; m++) {
        __syncthreads();
        for (int idx = threadIdx.x; idx < 4096; idx += 512)
            WT[(idx & 63) * 65 + (idx >> 6)] = Ws[m][idx];  // WT[d][c]=W[c][d]
        __syncthreads();
        float r = bs[m][c];
        #pragma unroll
        for (int d = 0; d < 64; d++) r += aggS[b * 64 + d] * WT[d * 65 + c];
        outs[m][((size_t)b * N_HEDGEK + u) * CCH + c] = r;
    }

    // w[b][u] = agg[b] . (Wv^T attR) + attR.bv
    __syncthreads();
    if (threadIdx.x < 64) {
        float sum = 0.f;
        for (int d = 0; d < 64; d++) sum += att[64 + d] * Wv[d * 64 + threadIdx.x];
        wvS[threadIdx.x] = sum;
    }
    if (threadIdx.x == 0) {
        float sum = 0.f;
        for (int d = 0; d < 64; d++) sum += att[64 + d] * bv[d];
        cbS = sum;
    }
    __syncthreads();
    float part = aggS[threadIdx.x] * wvS[c];
    #pragma unroll
    for (int d = 16; d; d >>= 1) part += __shfl_xor_sync(0xffffffffu, part, d);
    if ((threadIdx.x & 31) == 0) wred[threadIdx.x >> 5] = part;
    __syncthreads();
    if (c == 0) g_w[(size_t)b * N_HEDGEK + u] = wred[b * 2] + wred[b * 2 + 1] + cbS;
}

// ------------------------- masked edge-edge attention ------------------------
// a_e[u][b] = sum_v softmax(qk/8 - (1-adj)*500)[u,v] * w[b][v]
__global__ __launch_bounds__(256) void attn_kernel(const float* __restrict__ adj) {
    __shared__ float qS[16 * 64];
    __shared__ float kv[32 * 65];
    __shared__ float sc[16 * 512];
    __shared__ float wS[512];
    int b = blockIdx.y;
    int u0 = blockIdx.x * 16;
    int tid = threadIdx.x;
    const float* qb = g_q    + (size_t)b * N_HEDGEK * CCH;
    const float* kb = g_kmat + (size_t)b * N_HEDGEK * CCH;

    for (int idx = tid; idx < 16 * 64; idx += 256) qS[idx] = qb[u0 * 64 + idx];
    for (int idx = tid; idx < 512; idx += 256) wS[idx] = g_w[(size_t)b * N_HEDGEK + idx];

    int j = tid & 31, g = tid >> 5;
    int r0 = g, r1 = g + 8;
    for (int vt = 0; vt < 16; vt++) {
        __syncthreads();
        for (int idx = tid; idx < 32 * 64; idx += 256) {
            int row = idx >> 6, col = idx & 63;
            kv[row * 65 + col] = kb[(vt * 32 + row) * 64 + col];
        }
        __syncthreads();
        float a0 = 0.f, a1 = 0.f;
        #pragma unroll
        for (int c = 0; c < 64; c++) {
            float kvv = kv[j * 65 + c];
            a0 += qS[r0 * 64 + c] * kvv;
            a1 += qS[r1 * 64 + c] * kvv;
        }
        int v = vt * 32 + j;
        sc[r0 * 512 + v] = a0 * 0.125f - (1.f - adj[(u0 + r0) * 512 + v]) * 500.f;
        sc[r1 * 512 + v] = a1 * 0.125f - (1.f - adj[(u0 + r1) * 512 + v]) * 500.f;
    }
    __syncthreads();

    int lane = tid & 31, w = tid >> 5;
    #pragma unroll
    for (int rr = 0; rr < 2; rr++) {
        int r = w + rr * 8;
        float m = -1e30f;
        for (int vv = lane; vv < 512; vv += 32) m = fmaxf(m, sc[r * 512 + vv]);
        #pragma unroll
        for (int d = 16; d; d >>= 1) m = fmaxf(m, __shfl_xor_sync(0xffffffffu, m, d));
        float den = 0.f, num = 0.f;
        for (int vv = lane; vv < 512; vv += 32) {
            float e = __expf(sc[r * 512 + vv] - m);
            den += e;
            num += e * wS[vv];
        }
        #pragma unroll
        for (int d = 16; d; d >>= 1) {
            den += __shfl_xor_sync(0xffffffffu, den, d);
            num += __shfl_xor_sync(0xffffffffu, num, d);
        }
        if (lane == 0) g_ae[(u0 + r) * BBATCH + b] = num / den;
    }
}

// ------------------------- per-node segment softmax (ax fused) ---------------
__global__ __launch_bounds__(256) void node_softmax_kernel(
    const float* __restrict__ x, const float* __restrict__ att) {
    __shared__ float attS[64];
    if (threadIdx.x < 64) attS[threadIdx.x] = att[threadIdx.x];
    __syncthreads();
    int node = blockIdx.x * 8 + (threadIdx.x >> 5);
    if (node >= N_NODESK) return;
    int lane = threadIdx.x & 31;
    int b = lane & 7, sub = lane >> 3;
    int s = g_noff[node], e = g_noff[node + 1];
    if (s == e) return;

    const float4* row = (const float4*)(x + ((size_t)b * N_NODESK + node) * CCH + sub * 16);
    float p = 0.f;
    #pragma unroll
    for (int k = 0; k < 4; k++) {
        float4 v4 = row[k];
        const float* a = attS + sub * 16 + k * 4;
        p += v4.x * a[0] + v4.y * a[1] + v4.z * a[2] + v4.w * a[3];
    }
    p += __shfl_xor_sync(0xffffffffu, p, 8);
    p += __shfl_xor_sync(0xffffffffu, p, 16);
    float axv = p;

    float m = -1e30f;
    for (int q = s + sub; q < e; q += 4) {
        float v = axv + g_ae[g_csre[q] * BBATCH + b];
        v = v >= 0.f ? v : 0.2f * v;
        m = fmaxf(m, v);
    }
    m = fmaxf(m, __shfl_xor_sync(0xffffffffu, m, 8));
    m = fmaxf(m, __shfl_xor_sync(0xffffffffu, m, 16));
    float den = 0.f;
    for (int q = s + sub; q < e; q += 4) {
        float v = axv + g_ae[g_csre[q] * BBATCH + b];
        v = v >= 0.f ? v : 0.2f * v;
        den += __expf(v - m);
    }
    den += __shfl_xor_sync(0xffffffffu, den, 8);
    den += __shfl_xor_sync(0xffffffffu, den, 16);
    float inv = 1.f / (den + 1e-16f);
    for (int q = s + sub; q < e; q += 4) {
        int i = g_csr[q];
        float v = axv + g_ae[g_csre[q] * BBATCH + b];
        v = v >= 0.f ? v : 0.2f * v;
        g_alpha[i * BBATCH + b] = __expf(v - m) * inv;
    }
}

// ------------------------- stage 1: nodes -> hyperedges ----------------------
__global__ __launch_bounds__(512) void out1_kernel(const float* __restrict__ x) {
    __shared__ int nidx[96];
    __shared__ int seS[2];
    int u = blockIdx.x;
    if (threadIdx.x == 0) seS[0] = edge_lower_bound(u);
    if (threadIdx.x == 32) seS[1] = edge_lower_bound(u + 1);
    __syncthreads();
    int s = seS[0], e = seS[1], len = e - s;
    int b = threadIdx.x >> 6, c = threadIdx.x & 63;
    float acc = 0.f;
    for (int base = s; base < e; base += 96) {
        int cnt = min(96, e - base);
        __syncthreads();
        if (threadIdx.x < cnt) nidx[threadIdx.x] = g_nodes32[base + threadIdx.x];
        __syncthreads();
        for (int t = 0; t < cnt; t++) {
            float wgt = g_alpha[(base + t) * BBATCH + b];
            acc += wgt * x[((size_t)b * N_NODESK + nidx[t]) * CCH + c];
        }
    }
    float inv = (len > 0) ? (1.f / (float)len) : 0.f;   // Bn = 1/deg_e
    g_out1[u * (BBATCH * CCH) + threadIdx.x] = acc * inv;
}

// ------------------------- stage 2: hyperedges -> nodes ----------------------
__global__ __launch_bounds__(512) void out2_kernel(float* __restrict__ out) {
    int n = blockIdx.x;
    int b = threadIdx.x >> 6, c = threadIdx.x & 63;
    int s = g_noff[n], e = g_noff[n + 1];
    float acc = 0.f;
    for (int p = s; p < e; p++) {
        int i = g_csr[p];
        float wgt = g_alpha[i * BBATCH + b];
        acc += wgt * g_out1[g_csre[p] * (BBATCH * CCH) + threadIdx.x];
    }
    out[((size_t)b * N_NODESK + n) * CCH + c] = (float)(e - s) * acc;
}

// ------------------------- launch --------------------------------------------
extern "C" void kernel_launch(void* const* d_in, const int* in_sizes, int n_in,
                              void* d_out, int out_size) {
    const float* x   = (const float*)d_in[0];
    const float* Wq  = (const float*)d_in[1];
    const float* bq  = (const float*)d_in[2];
    const float* Wk  = (const float*)d_in[3];
    const float* bk  = (const float*)d_in[4];
    const float* Wv  = (const float*)d_in[5];
    const float* bv  = (const float*)d_in[6];
    const float* att = (const float*)d_in[7];
    const float* adj = (const float*)d_in[8];
    const void*  hei = (const void*)d_in[9];
    float* out = (float*)d_out;

    static cudaStream_t s1 = nullptr;
    static cudaEvent_t evP = nullptr, evA = nullptr;
    if (s1 == nullptr) {
        cudaStreamCreateWithFlags(&s1, cudaStreamNonBlocking);
        cudaEventCreateWithFlags(&evP, cudaEventDisableTiming);
        cudaEventCreateWithFlags(&evA, cudaEventDisableTiming);
    }

    zero_kernel<<<NBLK, 256>>>();
    prep_kernel<<<(N_INCK + 255) / 256, 256>>>(hei);
    cudaEventRecord(evP, 0);

    // edge-side chain on s1 (independent of the node CSR)
    cudaStreamWaitEvent(s1, evP, 0);
    aggqkv_kernel<<<N_HEDGEK, 512, 0, s1>>>(x, Wq, bq, Wk, bk, Wv, bv, att);
    attn_kernel<<<dim3(N_HEDGEK / 16, BBATCH), 256, 0, s1>>>(adj);
    cudaEventRecord(evA, s1);

    // node-side CSR chain on the captured stream (overlaps with s1)
    scan_local_kernel<<<NBLK, 256>>>();
    scan_add_kernel<<<NBLK, 256>>>();
    fill_kernel<<<(N_INCK + 255) / 256, 256>>>();

    cudaStreamWaitEvent(0, evA, 0);
    node_softmax_kernel<<<(N_NODESK + 7) / 8, 256>>>(x, att);
    out1_kernel<<<N_HEDGEK, 512>>>(x);
    out2_kernel<<<N_NODESK, 512>>>(out);
}